// round 5
// baseline (speedup 1.0000x reference)
#include <cuda_runtime.h>

#define NN 200000
#define NE 6400000

// Scratch (static device globals — no allocation allowed)
__device__ float  g_deg [NN];
__device__ float  g_dinv[NN];
__device__ float4 g_xn  [NN * 2];   // x*dinv, padded 7->8 floats per node
__device__ float4 g_acc1[NN * 2];   // sum over in-edges of xn[src] (7 used + pad)
__device__ float4 g_g2  [NN * 4];   // (h1@W2)*dinv : 16 f32 per node
__device__ float4 g_acc2[NN * 4];   // sum over in-edges of g2[src]

// ---------------------------------------------------------------------------
__global__ void k_init() {
    int i = blockIdx.x * blockDim.x + threadIdx.x;
    int stride = gridDim.x * blockDim.x;
    const float4 z = make_float4(0.f, 0.f, 0.f, 0.f);
    for (int j = i; j < NN * 2; j += stride) g_acc1[j] = z;
    for (int j = i; j < NN * 4; j += stride) g_acc2[j] = z;
    for (int j = i; j < NN;     j += stride) g_deg[j] = 1.0f;  // self-loop
}

__global__ void k_deg(const int* __restrict__ dst) {
    int i = blockIdx.x * blockDim.x + threadIdx.x;
    if (i < NE) atomicAdd(&g_deg[dst[i]], 1.0f);
}

// dinv = rsqrt(deg);  xn[i] = x[i] * dinv[i]  (padded to 8 floats)
__global__ void k_prep(const float* __restrict__ x) {
    int i = blockIdx.x * blockDim.x + threadIdx.x;
    if (i >= NN) return;
    float di = rsqrtf(g_deg[i]);
    g_dinv[i] = di;
    float v[8];
    #pragma unroll
    for (int k = 0; k < 7; k++) v[k] = x[i * 7 + k] * di;
    v[7] = 0.f;
    g_xn[i * 2 + 0] = make_float4(v[0], v[1], v[2], v[3]);
    g_xn[i * 2 + 1] = make_float4(v[4], v[5], v[6], v[7]);
}

// acc1[dst] += xn[src]   (2 x float4 vector REDs per edge)
__global__ void k_scatter1(const int* __restrict__ src,
                           const int* __restrict__ dst) {
    int e = blockIdx.x * blockDim.x + threadIdx.x;
    if (e >= NE) return;
    int s = src[e];
    int d = dst[e];
    float4 a = g_xn[s * 2 + 0];
    float4 b = g_xn[s * 2 + 1];
    atomicAdd(&g_acc1[d * 2 + 0], a);
    atomicAdd(&g_acc1[d * 2 + 1], b);
}

// agg = dinv*(acc1 + xn);  h1 = relu(agg@W1 + b1);  g2 = (h1@W2)*dinv
__global__ void k_fin1(const float* __restrict__ W1, const float* __restrict__ b1,
                       const float* __restrict__ W2) {
    __shared__ float sW1[7 * 32];
    __shared__ float sb1[32];
    __shared__ float sW2[32 * 16];
    int tid = threadIdx.x;
    if (tid < 7 * 32) sW1[tid] = W1[tid];
    if (tid < 32)     sb1[tid] = b1[tid];
    for (int j = tid; j < 32 * 16; j += blockDim.x) sW2[j] = W2[j];
    __syncthreads();
    int i = blockIdx.x * blockDim.x + tid;
    if (i >= NN) return;

    float di = g_dinv[i];
    float4 x0 = g_xn[i * 2 + 0];
    float4 x1 = g_xn[i * 2 + 1];
    float4 a0 = g_acc1[i * 2 + 0];
    float4 a1 = g_acc1[i * 2 + 1];
    float agg[7];
    agg[0] = di * (a0.x + x0.x);
    agg[1] = di * (a0.y + x0.y);
    agg[2] = di * (a0.z + x0.z);
    agg[3] = di * (a0.w + x0.w);
    agg[4] = di * (a1.x + x1.x);
    agg[5] = di * (a1.y + x1.y);
    agg[6] = di * (a1.z + x1.z);

    float h[32];
    #pragma unroll
    for (int j = 0; j < 32; j++) {
        float acc = sb1[j];
        #pragma unroll
        for (int k = 0; k < 7; k++) acc = fmaf(agg[k], sW1[k * 32 + j], acc);
        h[j] = fmaxf(acc, 0.f);
    }

    #pragma unroll
    for (int j = 0; j < 16; j += 4) {
        float4 o = make_float4(0.f, 0.f, 0.f, 0.f);
        #pragma unroll
        for (int k = 0; k < 32; k++) {
            float hk = h[k];
            o.x = fmaf(hk, sW2[k * 16 + j + 0], o.x);
            o.y = fmaf(hk, sW2[k * 16 + j + 1], o.y);
            o.z = fmaf(hk, sW2[k * 16 + j + 2], o.z);
            o.w = fmaf(hk, sW2[k * 16 + j + 3], o.w);
        }
        o.x *= di; o.y *= di; o.z *= di; o.w *= di;
        g_g2[i * 4 + (j >> 2)] = o;
    }
}

// acc2[dst] += g2[src]   (4 x float4 vector REDs per edge)
__global__ void k_scatter2(const int* __restrict__ src,
                           const int* __restrict__ dst) {
    int e = blockIdx.x * blockDim.x + threadIdx.x;
    if (e >= NE) return;
    int s = src[e];
    int d = dst[e];
    const float4* gs = &g_g2[s * 4];
    float4* ad = &g_acc2[d * 4];
    #pragma unroll
    for (int j = 0; j < 4; j++) atomicAdd(ad + j, gs[j]);
}

// h2 = relu(dinv*(acc2 + g2) + b2);  out = h2 @ Wfc + bfc
__global__ void k_fin2(const float* __restrict__ b2, const float* __restrict__ Wfc,
                       const float* __restrict__ bfc, float* __restrict__ out) {
    __shared__ float sW[16 * 2];
    __shared__ float sb2[16];
    __shared__ float sbf[2];
    int tid = threadIdx.x;
    if (tid < 32) sW[tid]  = Wfc[tid];
    if (tid < 16) sb2[tid] = b2[tid];
    if (tid < 2)  sbf[tid] = bfc[tid];
    __syncthreads();
    int i = blockIdx.x * blockDim.x + tid;
    if (i >= NN) return;

    float di = g_dinv[i];
    float o0 = sbf[0], o1 = sbf[1];
    #pragma unroll
    for (int j = 0; j < 16; j += 4) {
        float4 a = g_acc2[i * 4 + (j >> 2)];
        float4 g = g_g2  [i * 4 + (j >> 2)];
        float h0 = fmaxf(fmaf(a.x + g.x, di, sb2[j + 0]), 0.f);
        float h1 = fmaxf(fmaf(a.y + g.y, di, sb2[j + 1]), 0.f);
        float h2 = fmaxf(fmaf(a.z + g.z, di, sb2[j + 2]), 0.f);
        float h3 = fmaxf(fmaf(a.w + g.w, di, sb2[j + 3]), 0.f);
        o0 += h0 * sW[(j + 0) * 2 + 0] + h1 * sW[(j + 1) * 2 + 0]
            + h2 * sW[(j + 2) * 2 + 0] + h3 * sW[(j + 3) * 2 + 0];
        o1 += h0 * sW[(j + 0) * 2 + 1] + h1 * sW[(j + 1) * 2 + 1]
            + h2 * sW[(j + 2) * 2 + 1] + h3 * sW[(j + 3) * 2 + 1];
    }
    reinterpret_cast<float2*>(out)[i] = make_float2(o0, o1);
}

// ---------------------------------------------------------------------------
extern "C" void kernel_launch(void* const* d_in, const int* in_sizes, int n_in,
                              void* d_out, int out_size) {
    const float* x   = (const float*)d_in[0];
    const int*   ei  = (const int*)d_in[1];   // int32! (JAX default x64-disabled)
    const int*   src = ei;
    const int*   dst = ei + NE;
    const float* W1  = (const float*)d_in[2];
    const float* b1  = (const float*)d_in[3];
    const float* W2  = (const float*)d_in[4];
    const float* b2  = (const float*)d_in[5];
    const float* Wfc = (const float*)d_in[6];
    const float* bfc = (const float*)d_in[7];
    float* out = (float*)d_out;

    const int nt = 256;
    const int nb_nodes = (NN + nt - 1) / nt;
    const int nb_edges = (NE + nt - 1) / nt;

    k_init    <<<2048, nt>>>();
    k_deg     <<<nb_edges, nt>>>(dst);
    k_prep    <<<nb_nodes, nt>>>(x);
    k_scatter1<<<nb_edges, nt>>>(src, dst);
    k_fin1    <<<nb_nodes, nt>>>(W1, b1, W2);
    k_scatter2<<<nb_edges, nt>>>(src, dst);
    k_fin2    <<<nb_nodes, nt>>>(b2, Wfc, bfc, out);
}

// round 6
// speedup vs baseline: 1.1367x; 1.1367x over previous
#include <cuda_runtime.h>

#define NN 200000
#define NE 6400000
#define NB1 ((NN + 255) / 256)   // 782 blocks for node-sized scans

// Scratch (static device globals — no allocation allowed)
__device__ int    g_cnt [NN];        // in-degree (without self-loop)
__device__ int    g_off [NN];        // CSR segment start (exclusive scan of cnt)
__device__ int    g_cur [NN];        // fill cursor
__device__ int    g_bsum[1024];      // block sums for scan
__device__ int    g_csr [NE];        // src ids grouped by dst
__device__ float  g_dinv[NN];
__device__ float4 g_xn  [NN * 2];    // x*dinv padded 7->8
__device__ float4 g_g2  [NN * 4];    // (h1@W2)*dinv : 16 f32 per node

// ---------------------------------------------------------------------------
__global__ void k_zero() {
    int i = blockIdx.x * blockDim.x + threadIdx.x;
    if (i < NN) g_cnt[i] = 0;
}

__global__ void k_count(const int* __restrict__ dst) {
    int e = blockIdx.x * blockDim.x + threadIdx.x;
    if (e < NE) atomicAdd(&g_cnt[dst[e]], 1);
}

// per-block exclusive scan; block totals to g_bsum
__global__ void k_scan1() {
    __shared__ int sh[256];
    int tid = threadIdx.x;
    int i = blockIdx.x * 256 + tid;
    int v = (i < NN) ? g_cnt[i] : 0;
    sh[tid] = v;
    __syncthreads();
    #pragma unroll
    for (int ofs = 1; ofs < 256; ofs <<= 1) {
        int t = (tid >= ofs) ? sh[tid - ofs] : 0;
        __syncthreads();
        sh[tid] += t;
        __syncthreads();
    }
    if (i < NN) g_off[i] = sh[tid] - v;          // exclusive within block
    if (tid == 255) g_bsum[blockIdx.x] = sh[255]; // block total
}

// exclusive scan of the 782 block totals (single block)
__global__ void k_scan2() {
    __shared__ int sh[1024];
    int tid = threadIdx.x;
    int v = (tid < NB1) ? g_bsum[tid] : 0;
    sh[tid] = v;
    __syncthreads();
    #pragma unroll
    for (int ofs = 1; ofs < 1024; ofs <<= 1) {
        int t = (tid >= ofs) ? sh[tid - ofs] : 0;
        __syncthreads();
        sh[tid] += t;
        __syncthreads();
    }
    if (tid < NB1) g_bsum[tid] = sh[tid] - v;    // exclusive
}

__global__ void k_scan3() {
    int i = blockIdx.x * blockDim.x + threadIdx.x;
    if (i < NN) {
        int o = g_off[i] + g_bsum[i >> 8];
        g_off[i] = o;
        g_cur[i] = o;
    }
}

__global__ void k_fill(const int* __restrict__ src, const int* __restrict__ dst) {
    int e = blockIdx.x * blockDim.x + threadIdx.x;
    if (e >= NE) return;
    int p = atomicAdd(&g_cur[dst[e]], 1);
    g_csr[p] = src[e];
}

// dinv = rsqrt(deg+1);  xn[i] = x[i]*dinv[i]  (padded to 8 floats)
__global__ void k_prep(const float* __restrict__ x) {
    int i = blockIdx.x * blockDim.x + threadIdx.x;
    if (i >= NN) return;
    float di = rsqrtf((float)(g_cnt[i] + 1));    // +1 self-loop
    g_dinv[i] = di;
    float v[8];
    #pragma unroll
    for (int k = 0; k < 7; k++) v[k] = x[i * 7 + k] * di;
    v[7] = 0.f;
    g_xn[i * 2 + 0] = make_float4(v[0], v[1], v[2], v[3]);
    g_xn[i * 2 + 1] = make_float4(v[4], v[5], v[6], v[7]);
}

// Gather layer-1 (pre-W1 features) + fused MLP:  g2 = (relu(agg@W1+b1)@W2)*dinv
__global__ void k_g1(const float* __restrict__ W1, const float* __restrict__ b1,
                     const float* __restrict__ W2) {
    __shared__ float sW1[7 * 32];
    __shared__ float sb1[32];
    __shared__ float sW2[32 * 16];
    int tid = threadIdx.x;
    if (tid < 7 * 32) sW1[tid] = W1[tid];
    if (tid < 32)     sb1[tid] = b1[tid];
    for (int j = tid; j < 32 * 16; j += blockDim.x) sW2[j] = W2[j];
    __syncthreads();
    int i = blockIdx.x * blockDim.x + tid;
    if (i >= NN) return;

    float4 a0 = g_xn[i * 2 + 0];   // self term
    float4 a1 = g_xn[i * 2 + 1];
    int beg = g_off[i];
    int end = beg + g_cnt[i];
    for (int p = beg; p < end; ++p) {
        int s = g_csr[p];
        float4 u = g_xn[s * 2 + 0];
        float4 v = g_xn[s * 2 + 1];
        a0.x += u.x; a0.y += u.y; a0.z += u.z; a0.w += u.w;
        a1.x += v.x; a1.y += v.y; a1.z += v.z;
    }
    float di = g_dinv[i];
    float agg[7] = { a0.x * di, a0.y * di, a0.z * di, a0.w * di,
                     a1.x * di, a1.y * di, a1.z * di };

    float h[32];
    #pragma unroll
    for (int j = 0; j < 32; j++) {
        float acc = sb1[j];
        #pragma unroll
        for (int k = 0; k < 7; k++) acc = fmaf(agg[k], sW1[k * 32 + j], acc);
        h[j] = fmaxf(acc, 0.f);
    }

    #pragma unroll
    for (int j = 0; j < 16; j += 4) {
        float4 o = make_float4(0.f, 0.f, 0.f, 0.f);
        #pragma unroll
        for (int k = 0; k < 32; k++) {
            float hk = h[k];
            o.x = fmaf(hk, sW2[k * 16 + j + 0], o.x);
            o.y = fmaf(hk, sW2[k * 16 + j + 1], o.y);
            o.z = fmaf(hk, sW2[k * 16 + j + 2], o.z);
            o.w = fmaf(hk, sW2[k * 16 + j + 3], o.w);
        }
        o.x *= di; o.y *= di; o.z *= di; o.w *= di;
        g_g2[i * 4 + (j >> 2)] = o;
    }
}

// Gather layer-2 + fused FC:  out = relu(dinv*(Σ g2) + b2) @ Wfc + bfc
__global__ void k_g2(const float* __restrict__ b2, const float* __restrict__ Wfc,
                     const float* __restrict__ bfc, float* __restrict__ out) {
    __shared__ float sW[16 * 2];
    __shared__ float sb2[16];
    __shared__ float sbf[2];
    int tid = threadIdx.x;
    if (tid < 32) sW[tid]  = Wfc[tid];
    if (tid < 16) sb2[tid] = b2[tid];
    if (tid < 2)  sbf[tid] = bfc[tid];
    __syncthreads();
    int i = blockIdx.x * blockDim.x + tid;
    if (i >= NN) return;

    float4 a0 = g_g2[i * 4 + 0];   // self term
    float4 a1 = g_g2[i * 4 + 1];
    float4 a2 = g_g2[i * 4 + 2];
    float4 a3 = g_g2[i * 4 + 3];
    int beg = g_off[i];
    int end = beg + g_cnt[i];
    for (int p = beg; p < end; ++p) {
        int s = g_csr[p];
        const float4* gs = &g_g2[s * 4];
        float4 u = gs[0], v = gs[1], w = gs[2], z = gs[3];
        a0.x += u.x; a0.y += u.y; a0.z += u.z; a0.w += u.w;
        a1.x += v.x; a1.y += v.y; a1.z += v.z; a1.w += v.w;
        a2.x += w.x; a2.y += w.y; a2.z += w.z; a2.w += w.w;
        a3.x += z.x; a3.y += z.y; a3.z += z.z; a3.w += z.w;
    }
    float di = g_dinv[i];
    float h[16];
    h[0]=fmaxf(fmaf(a0.x,di,sb2[0]),0.f);  h[1]=fmaxf(fmaf(a0.y,di,sb2[1]),0.f);
    h[2]=fmaxf(fmaf(a0.z,di,sb2[2]),0.f);  h[3]=fmaxf(fmaf(a0.w,di,sb2[3]),0.f);
    h[4]=fmaxf(fmaf(a1.x,di,sb2[4]),0.f);  h[5]=fmaxf(fmaf(a1.y,di,sb2[5]),0.f);
    h[6]=fmaxf(fmaf(a1.z,di,sb2[6]),0.f);  h[7]=fmaxf(fmaf(a1.w,di,sb2[7]),0.f);
    h[8]=fmaxf(fmaf(a2.x,di,sb2[8]),0.f);  h[9]=fmaxf(fmaf(a2.y,di,sb2[9]),0.f);
    h[10]=fmaxf(fmaf(a2.z,di,sb2[10]),0.f); h[11]=fmaxf(fmaf(a2.w,di,sb2[11]),0.f);
    h[12]=fmaxf(fmaf(a3.x,di,sb2[12]),0.f); h[13]=fmaxf(fmaf(a3.y,di,sb2[13]),0.f);
    h[14]=fmaxf(fmaf(a3.z,di,sb2[14]),0.f); h[15]=fmaxf(fmaf(a3.w,di,sb2[15]),0.f);

    float o0 = sbf[0], o1 = sbf[1];
    #pragma unroll
    for (int j = 0; j < 16; j++) {
        o0 = fmaf(h[j], sW[j * 2 + 0], o0);
        o1 = fmaf(h[j], sW[j * 2 + 1], o1);
    }
    reinterpret_cast<float2*>(out)[i] = make_float2(o0, o1);
}

// ---------------------------------------------------------------------------
extern "C" void kernel_launch(void* const* d_in, const int* in_sizes, int n_in,
                              void* d_out, int out_size) {
    const float* x   = (const float*)d_in[0];
    const int*   ei  = (const int*)d_in[1];   // int32 (JAX x64 disabled)
    const int*   src = ei;
    const int*   dst = ei + NE;
    const float* W1  = (const float*)d_in[2];
    const float* b1  = (const float*)d_in[3];
    const float* W2  = (const float*)d_in[4];
    const float* b2  = (const float*)d_in[5];
    const float* Wfc = (const float*)d_in[6];
    const float* bfc = (const float*)d_in[7];
    float* out = (float*)d_out;

    const int nt = 256;
    const int nb_nodes = NB1;
    const int nb_edges = (NE + nt - 1) / nt;

    k_zero  <<<nb_nodes, nt>>>();
    k_count <<<nb_edges, nt>>>(dst);
    k_scan1 <<<nb_nodes, nt>>>();
    k_scan2 <<<1, 1024>>>();
    k_scan3 <<<nb_nodes, nt>>>();
    k_fill  <<<nb_edges, nt>>>(src, dst);
    k_prep  <<<nb_nodes, nt>>>(x);
    k_g1    <<<nb_nodes, nt>>>(W1, b1, W2);
    k_g2    <<<nb_nodes, nt>>>(b2, Wfc, bfc, out);
}